// round 13
// baseline (speedup 1.0000x reference)
#include <cuda_runtime.h>

#define BB 4
#define NH 8
#define DD 16
#define LC 1024
#define WCC 32
#define LF 4096
#define WFF 64
#define TOPK 8
#define KVPAD 20

typedef unsigned long long ull;

__device__ float g_qc[BB*NH*LC*DD];
__device__ float g_kc[BB*NH*LC*DD];
__device__ float g_vc[BB*NH*LC*DD];
__device__ float g_qf[BB*NH*LF*DD];
__device__ float g_kf[BB*NH*LF*DD];
__device__ float g_vf[BB*NH*LF*DD];
__device__ float g_msg0[BB*NH*LC*DD];
__device__ int   g_topk[BB*NH*LC*TOPK];

__device__ __forceinline__ float2 f2unpack(ull v) {
    float lo, hi; asm("mov.b64 {%0, %1}, %2;" : "=f"(lo), "=f"(hi) : "l"(v));
    return make_float2(lo, hi);
}
__device__ __forceinline__ ull f2dup(float x) {
    ull r; asm("mov.b64 %0, {%1, %1};" : "=l"(r) : "f"(x)); return r;
}
__device__ __forceinline__ ull f2fma(ull a, ull b, ull c) {
    ull d; asm("fma.rn.f32x2 %0, %1, %2, %3;" : "=l"(d) : "l"(a), "l"(b), "l"(c));
    return d;
}
__device__ __forceinline__ ull f2add(ull a, ull b) {
    ull d; asm("add.rn.f32x2 %0, %1, %2;" : "=l"(d) : "l"(a), "l"(b));
    return d;
}
__device__ __forceinline__ float ex2f(float x) {
    float r; asm("ex2.approx.ftz.f32 %0, %1;" : "=f"(r) : "f"(x)); return r;
}
__device__ __forceinline__ unsigned fsort(float f) {
    unsigned u = __float_as_uint(f);
    return u ^ (((unsigned)((int)u >> 31)) | 0x80000000u);
}

// ---------------- tiled transpose: [BH,16,P] -> [BH,P,16] ----------------
__global__ void __launch_bounds__(256) transpose3_kernel(
        const float* __restrict__ q, const float* __restrict__ k,
        const float* __restrict__ v, float* __restrict__ oq,
        float* __restrict__ ok, float* __restrict__ ov, int P, float qscale) {
    __shared__ float tile[16 * 260];
    int z = blockIdx.z;
    const float* in = (z == 0) ? q : (z == 1) ? k : v;
    float* out = (z == 0) ? oq : (z == 1) ? ok : ov;
    float scale = (z == 0) ? qscale : 1.f;
    int bh = blockIdx.y, p0 = blockIdx.x * 256, t = threadIdx.x;
    const float4* src = reinterpret_cast<const float4*>(in + (size_t)bh * DD * P + p0);
    int Pq = P >> 2;
#pragma unroll
    for (int j = 0; j < 4; j++) {
        int f = t + 256 * j;
        int d = f >> 6, c4 = f & 63;
        float4 val = src[(size_t)d * Pq + c4];
        val.x *= scale; val.y *= scale; val.z *= scale; val.w *= scale;
        *reinterpret_cast<float4*>(&tile[d * 260 + c4 * 4]) = val;
    }
    __syncthreads();
    float o[16];
#pragma unroll
    for (int d = 0; d < 16; d++) o[d] = tile[d * 260 + t];
    float4* dst = reinterpret_cast<float4*>(out + ((size_t)bh * P + p0 + t) * DD);
    dst[0] = make_float4(o[0], o[1], o[2], o[3]);
    dst[1] = make_float4(o[4], o[5], o[6], o[7]);
    dst[2] = make_float4(o[8], o[9], o[10], o[11]);
    dst[3] = make_float4(o[12], o[13], o[14], o[15]);
}

// ---------------- coarse: lane-pair per row, 512 thr, 1 wave -------------
// Lane pair shares a row; even lane does even columns, odd lane odd columns.
// Warp reads rows 2i,2i+1 = contiguous 128B -> 1 wavefront per LDS.128.
#define CSMEM_BYTES (2 * LC * DD * 4)

__global__ void __launch_bounds__(512, 1) coarse_kernel() {
    extern __shared__ float sm[];
    float* sK = sm;             // 1024 x 16 contiguous
    float* sV = sm + LC * DD;   // 1024 x 16
    int tid = threadIdx.x, w = tid >> 5, lane = tid & 31;
    int bh = blockIdx.y;

    {
        const float4* K4 = (const float4*)(g_kc + (size_t)bh * LC * DD);
        const float4* V4 = (const float4*)(g_vc + (size_t)bh * LC * DD);
        float4* sK4 = (float4*)sK;
        float4* sV4 = (float4*)sV;
#pragma unroll
        for (int i = tid; i < LC * DD / 4; i += 512) {
            sK4[i] = K4[i];
            sV4[i] = V4[i];
        }
    }

    int row = blockIdx.x * 256 + w * 16 + (lane >> 1);
    int par = lane & 1;
    const ull* Qg = (const ull*)(g_qc + ((size_t)bh * LC + row) * DD);
    ull q[8];
#pragma unroll
    for (int dp = 0; dp < 8; dp++) q[dp] = Qg[dp];
    __syncthreads();

    float tv[8]; int tc[8];
#pragma unroll
    for (int k = 0; k < 8; k++) { tv[k] = -3e38f; tc[k] = 0; }
    ull acc[8];
#pragma unroll
    for (int dp = 0; dp < 8; dp++) acc[dp] = 0ull;
    float sum = 0.f;

#pragma unroll 2
    for (int i = 0; i < LC / 2; i++) {
        int j = 2 * i + par;
        const ull* kr = (const ull*)(sK + j * DD);
        ull a0 = 0ull, a1 = 0ull;
        a0 = f2fma(q[0], kr[0], a0); a1 = f2fma(q[1], kr[1], a1);
        a0 = f2fma(q[2], kr[2], a0); a1 = f2fma(q[3], kr[3], a1);
        a0 = f2fma(q[4], kr[4], a0); a1 = f2fma(q[5], kr[5], a1);
        a0 = f2fma(q[6], kr[6], a0); a1 = f2fma(q[7], kr[7], a1);
        float2 u = f2unpack(f2add(a0, a1));
        float sc = u.x + u.y;
        float e = ex2f(sc);            // log2e folded into Q scale
        sum += e;
        ull ed = f2dup(e);
        const ull* vr = (const ull*)(sV + j * DD);
#pragma unroll
        for (int dp = 0; dp < 8; dp++) acc[dp] = f2fma(ed, vr[dp], acc[dp]);
        // exact per-lane top-8: strict > + ascending j == lax.top_k ties
        if (sc > tv[7]) {
            tv[7] = sc; tc[7] = j;
#pragma unroll
            for (int k = 7; k >= 1; k--) {
                bool sw = tv[k] > tv[k - 1];
                float va = sw ? tv[k - 1] : tv[k];
                float vb = sw ? tv[k] : tv[k - 1];
                int ia = sw ? tc[k - 1] : tc[k];
                int ib = sw ? tc[k] : tc[k - 1];
                tv[k] = va; tv[k - 1] = vb;
                tc[k] = ia; tc[k - 1] = ib;
            }
        }
    }

    // ---- pair merge (lane ^ 1): sums, accumulators, exact top-8 set ----
    sum += __shfl_xor_sync(0xffffffffu, sum, 1);
#pragma unroll
    for (int dp = 0; dp < 8; dp++)
        acc[dp] = f2add(acc[dp], __shfl_xor_sync(0xffffffffu, acc[dp], 1));

    // packed keys: value desc, lower j wins ties (2047 - j in low bits)
    ull key[8], ok[8];
#pragma unroll
    for (int k = 0; k < 8; k++)
        key[k] = ((ull)fsort(tv[k]) << 32) | (unsigned)(2047 - tc[k]);
#pragma unroll
    for (int k = 0; k < 8; k++)
        ok[k] = __shfl_xor_sync(0xffffffffu, key[k], 1);
    // bitonic half-cleaner: top-8 multiset of the two desc-sorted lists
#pragma unroll
    for (int k = 0; k < 8; k++) {
        ull o = ok[7 - k];
        if (o > key[k]) key[k] = o;
    }

    if (par == 0) {
        int* tb = g_topk + ((size_t)bh * LC + row) * TOPK;
        int t0 = 2047 - (int)(key[0] & 0xffffffffu);
        int t1 = 2047 - (int)(key[1] & 0xffffffffu);
        int t2 = 2047 - (int)(key[2] & 0xffffffffu);
        int t3 = 2047 - (int)(key[3] & 0xffffffffu);
        *(int4*)tb = make_int4(t0, t1, t2, t3);
        t0 = 2047 - (int)(key[4] & 0xffffffffu);
        t1 = 2047 - (int)(key[5] & 0xffffffffu);
        t2 = 2047 - (int)(key[6] & 0xffffffffu);
        t3 = 2047 - (int)(key[7] & 0xffffffffu);
        *(int4*)(tb + 4) = make_int4(t0, t1, t2, t3);

        float rs = 1.f / sum;
        float o[16];
#pragma unroll
        for (int dp = 0; dp < 8; dp++) {
            float2 u = f2unpack(acc[dp]);
            o[2 * dp] = u.x * rs;
            o[2 * dp + 1] = u.y * rs;
        }
        float4* mp = (float4*)(g_msg0 + ((size_t)bh * LC + row) * DD);
        mp[0] = make_float4(o[0], o[1], o[2], o[3]);
        mp[1] = make_float4(o[4], o[5], o[6], o[7]);
        mp[2] = make_float4(o[8], o[9], o[10], o[11]);
        mp[3] = make_float4(o[12], o[13], o[14], o[15]);
    }
}

// ---------------- fine level + combine ----------------
__device__ __forceinline__ float dot16(float4 a0, float4 a1, float4 a2, float4 a3,
                                       float4 b0, float4 b1, float4 b2, float4 b3) {
    float s = a0.x*b0.x + a0.y*b0.y + a0.z*b0.z + a0.w*b0.w;
    s += a1.x*b1.x + a1.y*b1.y + a1.z*b1.z + a1.w*b1.w;
    s += a2.x*b2.x + a2.y*b2.y + a2.z*b2.z + a2.w*b2.w;
    s += a3.x*b3.x + a3.y*b3.y + a3.z*b3.z + a3.w*b3.w;
    return s;
}

__global__ void __launch_bounds__(256) fine_kernel(const float* __restrict__ wptr,
                                                   float* __restrict__ out) {
    __shared__ float sQ[8][4][16];
    __shared__ float sKP[8][32][KVPAD];   // K tiles, later overlaid by P
    __shared__ float sV[8][32][KVPAD];
    int tid = threadIdx.x, w = tid >> 5, lane = tid & 31;
    int gw = blockIdx.x * 8 + w;
    int bh = gw >> 10, l = gw & 1023;
    int b = bh >> 3, h = bh & 7;
    int lh = l >> 5, lw = l & 31;

    float w0 = wptr[0], w1 = wptr[1];
    float mw = fmaxf(w0, w1);
    float ew0 = __expf(w0 - mw), ew1 = __expf(w1 - mw);
    float rw = __fdividef(1.f, ew0 + ew1);
    float wa = ew0 * rw, wb = ew1 * rw;

    int cr = lane >> 2, off2 = lane & 3, ox = off2 >> 1, oy = off2 & 1;
    int cidx = g_topk[((size_t)bh * LC + l) * TOPK + cr];
    int py = cidx >> 5, px = cidx & (WCC - 1);
    int pos = (2 * py + ox) * WFF + 2 * px + oy;

    if (lane < 16) {
        int qq = lane >> 2, j = lane & 3;
        int qpos = (2 * lh + (qq >> 1)) * WFF + 2 * lw + (qq & 1);
        float4 qv = ((const float4*)(g_qf + ((size_t)bh * LF + qpos) * DD))[j];
        *reinterpret_cast<float4*>(&sQ[w][qq][4 * j]) = qv;
    }

    const float* kbase = g_kf + (size_t)bh * LF * DD;
    const float* vbase = g_vf + (size_t)bh * LF * DD;
    int cj = lane >> 2, j4 = (lane & 3) * 4;
#pragma unroll
    for (int rep = 0; rep < 4; rep++) {
        int c = rep * 8 + cj;
        int pc = __shfl_sync(0xffffffffu, pos, c);
        float4 kv = *(const float4*)(kbase + (size_t)pc * DD + j4);
        *reinterpret_cast<float4*>(&sKP[w][c][j4]) = kv;
        float4 vv = *(const float4*)(vbase + (size_t)pc * DD + j4);
        *reinterpret_cast<float4*>(&sV[w][c][j4]) = vv;
    }
    __syncwarp();

    const float* kp = &sKP[w][lane][0];
    float4 k0 = *(const float4*)(kp);
    float4 k1 = *(const float4*)(kp + 4);
    float4 k2 = *(const float4*)(kp + 8);
    float4 k3 = *(const float4*)(kp + 12);
    __syncwarp();   // all k regs loaded before P overlays the buffer

    float p[4];
#pragma unroll
    for (int qq = 0; qq < 4; qq++) {
        const float4* q4 = (const float4*)sQ[w][qq];
        float sc = dot16(q4[0], q4[1], q4[2], q4[3], k0, k1, k2, k3);
        float m = sc;
#pragma unroll
        for (int o = 16; o; o >>= 1) m = fmaxf(m, __shfl_xor_sync(0xffffffffu, m, o));
        float e = ex2f(sc - m);
        float s = e;
#pragma unroll
        for (int o = 16; o; o >>= 1) s += __shfl_xor_sync(0xffffffffu, s, o);
        p[qq] = __fdividef(e, s);
    }
    *reinterpret_cast<float4*>(&sKP[w][lane][0]) = make_float4(p[0], p[1], p[2], p[3]);
    __syncwarp();

    int qq = lane >> 3, dp = lane & 7, d0 = dp * 2;
    float accx = 0.f, accy = 0.f;
#pragma unroll
    for (int c = 0; c < 32; c++) {
        float pc = sKP[w][c][qq];
        float2 vv = *reinterpret_cast<const float2*>(&sV[w][c][d0]);
        accx += pc * vv.x;
        accy += pc * vv.y;
    }
    const float* m0p = g_msg0 + ((size_t)bh * LC + l) * DD + d0;
    float o0 = wa * m0p[0] + wb * accx;
    float o1 = wa * m0p[1] + wb * accy;
    int opos = (2 * lh + (qq >> 1)) * WFF + 2 * lw + (qq & 1);
    float* op = out + (((size_t)b * LF + opos) * NH + h) * DD + d0;
    *reinterpret_cast<float2*>(op) = make_float2(o0, o1);
}

extern "C" void kernel_launch(void* const* d_in, const int* in_sizes, int n_in,
                              void* d_out, int out_size) {
    (void)in_sizes; (void)n_in; (void)out_size;
    const float* qf = (const float*)d_in[0];
    const float* qc = (const float*)d_in[1];
    const float* kf = (const float*)d_in[2];
    const float* kc = (const float*)d_in[3];
    const float* vf = (const float*)d_in[4];
    const float* vc = (const float*)d_in[5];
    const float* wt = (const float*)d_in[6];
    float* out = (float*)d_out;

    void *p_qc, *p_kc, *p_vc, *p_qf, *p_kf, *p_vf;
    cudaGetSymbolAddress(&p_qc, g_qc);
    cudaGetSymbolAddress(&p_kc, g_kc);
    cudaGetSymbolAddress(&p_vc, g_vc);
    cudaGetSymbolAddress(&p_qf, g_qf);
    cudaGetSymbolAddress(&p_kf, g_kf);
    cudaGetSymbolAddress(&p_vf, g_vf);

    const float qscale = 0.25f * 1.4426950408889634f;  // temp * log2(e)
    transpose3_kernel<<<dim3(LC / 256, 32, 3), 256>>>(
        qc, kc, vc, (float*)p_qc, (float*)p_kc, (float*)p_vc, LC, qscale);
    transpose3_kernel<<<dim3(LF / 256, 32, 3), 256>>>(
        qf, kf, vf, (float*)p_qf, (float*)p_kf, (float*)p_vf, LF, qscale);

    cudaFuncSetAttribute(coarse_kernel, cudaFuncAttributeMaxDynamicSharedMemorySize,
                         CSMEM_BYTES);
    coarse_kernel<<<dim3(4, 32), 512, CSMEM_BYTES>>>();

    fine_kernel<<<4096, 256>>>(wt, out);
}

// round 14
// speedup vs baseline: 1.5542x; 1.5542x over previous
#include <cuda_runtime.h>

#define BB 4
#define NH 8
#define DD 16
#define LC 1024
#define WCC 32
#define LF 4096
#define WFF 64
#define TOPK 8
#define KVPAD 20

typedef unsigned long long ull;

__device__ float g_qc[BB*NH*LC*DD];
__device__ float g_kc[BB*NH*LC*DD];
__device__ float g_vc[BB*NH*LC*DD];
__device__ float g_qf[BB*NH*LF*DD];
__device__ float g_kf[BB*NH*LF*DD];
__device__ float g_vf[BB*NH*LF*DD];
__device__ float g_msg0[BB*NH*LC*DD];
__device__ int   g_topk[BB*NH*LC*TOPK];

__device__ __forceinline__ float2 f2unpack(ull v) {
    float lo, hi; asm("mov.b64 {%0, %1}, %2;" : "=f"(lo), "=f"(hi) : "l"(v));
    return make_float2(lo, hi);
}
__device__ __forceinline__ ull f2dup(float x) {
    ull r; asm("mov.b64 %0, {%1, %1};" : "=l"(r) : "f"(x)); return r;
}
__device__ __forceinline__ ull f2fma(ull a, ull b, ull c) {
    ull d; asm("fma.rn.f32x2 %0, %1, %2, %3;" : "=l"(d) : "l"(a), "l"(b), "l"(c));
    return d;
}
__device__ __forceinline__ ull f2add(ull a, ull b) {
    ull d; asm("add.rn.f32x2 %0, %1, %2;" : "=l"(d) : "l"(a), "l"(b));
    return d;
}
__device__ __forceinline__ float ex2f(float x) {
    float r; asm("ex2.approx.ftz.f32 %0, %1;" : "=f"(r) : "f"(x)); return r;
}

// ---------------- tiled transpose: [BH,16,P] -> [BH,P,16] ----------------
__global__ void __launch_bounds__(256) transpose3_kernel(
        const float* __restrict__ q, const float* __restrict__ k,
        const float* __restrict__ v, float* __restrict__ oq,
        float* __restrict__ ok, float* __restrict__ ov, int P, float qscale) {
    __shared__ float tile[16 * 260];
    int z = blockIdx.z;
    const float* in = (z == 0) ? q : (z == 1) ? k : v;
    float* out = (z == 0) ? oq : (z == 1) ? ok : ov;
    float scale = (z == 0) ? qscale : 1.f;
    int bh = blockIdx.y, p0 = blockIdx.x * 256, t = threadIdx.x;
    const float4* src = reinterpret_cast<const float4*>(in + (size_t)bh * DD * P + p0);
    int Pq = P >> 2;
#pragma unroll
    for (int j = 0; j < 4; j++) {
        int f = t + 256 * j;
        int d = f >> 6, c4 = f & 63;
        float4 val = src[(size_t)d * Pq + c4];
        val.x *= scale; val.y *= scale; val.z *= scale; val.w *= scale;
        *reinterpret_cast<float4*>(&tile[d * 260 + c4 * 4]) = val;
    }
    __syncthreads();
    float o[16];
#pragma unroll
    for (int d = 0; d < 16; d++) o[d] = tile[d * 260 + t];
    float4* dst = reinterpret_cast<float4*>(out + ((size_t)bh * P + p0 + t) * DD);
    dst[0] = make_float4(o[0], o[1], o[2], o[3]);
    dst[1] = make_float4(o[4], o[5], o[6], o[7]);
    dst[2] = make_float4(o[8], o[9], o[10], o[11]);
    dst[3] = make_float4(o[12], o[13], o[14], o[15]);
}

// ---------------- coarse: lane-per-row, prefetch-pipelined, 1 wave -------
#define CSMEM_BYTES (2 * LC * DD * 4)

__device__ __forceinline__ void loadrow(const float* __restrict__ p, ull* r) {
    const ull* u = (const ull*)p;
#pragma unroll
    for (int dp = 0; dp < 8; dp++) r[dp] = u[dp];
}

__global__ void __launch_bounds__(256, 1) coarse_kernel() {
    extern __shared__ float sm[];
    float* sK = sm;             // 1024 x 16, contiguous (broadcast reads)
    float* sV = sm + LC * DD;   // 1024 x 16
    int tid = threadIdx.x, w = tid >> 5, lane = tid & 31;
    int bh = blockIdx.y;

    {
        const float4* K4 = (const float4*)(g_kc + (size_t)bh * LC * DD);
        const float4* V4 = (const float4*)(g_vc + (size_t)bh * LC * DD);
        float4* sK4 = (float4*)sK;
        float4* sV4 = (float4*)sV;
#pragma unroll
        for (int i = tid; i < LC * DD / 4; i += 256) {
            sK4[i] = K4[i];
            sV4[i] = V4[i];
        }
    }

    int row = blockIdx.x * 256 + w * 32 + lane;
    const ull* Qg = (const ull*)(g_qc + ((size_t)bh * LC + row) * DD);
    ull q[8];
#pragma unroll
    for (int dp = 0; dp < 8; dp++) q[dp] = Qg[dp];
    __syncthreads();

    float tv[8]; int tc[8];
#pragma unroll
    for (int k = 0; k < 8; k++) { tv[k] = -3e38f; tc[k] = 0; }
    ull acc[8];
#pragma unroll
    for (int dp = 0; dp < 8; dp++) acc[dp] = 0ull;
    float sum = 0.f;

    // software pipeline: K/V row j+1 prefetched while computing row j
    ull kr[8], vr[8];
    loadrow(sK, kr);
    loadrow(sV, vr);

#pragma unroll 2
    for (int j = 0; j < LC; j++) {
        int jn = (j + 1) & (LC - 1);
        ull kn[8], vn[8];
        loadrow(sK + jn * DD, kn);
        loadrow(sV + jn * DD, vn);

        ull a0 = 0ull, a1 = 0ull;
        a0 = f2fma(q[0], kr[0], a0); a1 = f2fma(q[1], kr[1], a1);
        a0 = f2fma(q[2], kr[2], a0); a1 = f2fma(q[3], kr[3], a1);
        a0 = f2fma(q[4], kr[4], a0); a1 = f2fma(q[5], kr[5], a1);
        a0 = f2fma(q[6], kr[6], a0); a1 = f2fma(q[7], kr[7], a1);
        float2 u = f2unpack(f2add(a0, a1));
        float sc = u.x + u.y;
        float e = ex2f(sc);            // log2e folded into Q scale
        sum += e;
        ull ed = f2dup(e);
#pragma unroll
        for (int dp = 0; dp < 8; dp++) acc[dp] = f2fma(ed, vr[dp], acc[dp]);
        // exact top-8: strict > + ascending j == lax.top_k tie semantics
        if (sc > tv[7]) {
            tv[7] = sc; tc[7] = j;
#pragma unroll
            for (int k = 7; k >= 1; k--) {
                bool sw = tv[k] > tv[k - 1];
                float va = sw ? tv[k - 1] : tv[k];
                float vb = sw ? tv[k] : tv[k - 1];
                int ia = sw ? tc[k - 1] : tc[k];
                int ib = sw ? tc[k] : tc[k - 1];
                tv[k] = va; tv[k - 1] = vb;
                tc[k] = ia; tc[k - 1] = ib;
            }
        }
#pragma unroll
        for (int dp = 0; dp < 8; dp++) { kr[dp] = kn[dp]; vr[dp] = vn[dp]; }
    }

    int* tb = g_topk + ((size_t)bh * LC + row) * TOPK;
    *(int4*)tb = make_int4(tc[0], tc[1], tc[2], tc[3]);
    *(int4*)(tb + 4) = make_int4(tc[4], tc[5], tc[6], tc[7]);

    float rs = 1.f / sum;
    float o[16];
#pragma unroll
    for (int dp = 0; dp < 8; dp++) {
        float2 u = f2unpack(acc[dp]);
        o[2 * dp] = u.x * rs;
        o[2 * dp + 1] = u.y * rs;
    }
    float4* mp = (float4*)(g_msg0 + ((size_t)bh * LC + row) * DD);
    mp[0] = make_float4(o[0], o[1], o[2], o[3]);
    mp[1] = make_float4(o[4], o[5], o[6], o[7]);
    mp[2] = make_float4(o[8], o[9], o[10], o[11]);
    mp[3] = make_float4(o[12], o[13], o[14], o[15]);
}

// ---------------- fine level + combine ----------------
__device__ __forceinline__ float dot16(float4 a0, float4 a1, float4 a2, float4 a3,
                                       float4 b0, float4 b1, float4 b2, float4 b3) {
    float s = a0.x*b0.x + a0.y*b0.y + a0.z*b0.z + a0.w*b0.w;
    s += a1.x*b1.x + a1.y*b1.y + a1.z*b1.z + a1.w*b1.w;
    s += a2.x*b2.x + a2.y*b2.y + a2.z*b2.z + a2.w*b2.w;
    s += a3.x*b3.x + a3.y*b3.y + a3.z*b3.z + a3.w*b3.w;
    return s;
}

__global__ void __launch_bounds__(256) fine_kernel(const float* __restrict__ wptr,
                                                   float* __restrict__ out) {
    __shared__ float sQ[8][4][16];
    __shared__ float sKP[8][32][KVPAD];   // K tiles, later overlaid by P
    __shared__ float sV[8][32][KVPAD];
    int tid = threadIdx.x, w = tid >> 5, lane = tid & 31;
    int gw = blockIdx.x * 8 + w;
    int bh = gw >> 10, l = gw & 1023;
    int b = bh >> 3, h = bh & 7;
    int lh = l >> 5, lw = l & 31;

    float w0 = wptr[0], w1 = wptr[1];
    float mw = fmaxf(w0, w1);
    float ew0 = __expf(w0 - mw), ew1 = __expf(w1 - mw);
    float rw = __fdividef(1.f, ew0 + ew1);
    float wa = ew0 * rw, wb = ew1 * rw;

    int cr = lane >> 2, off2 = lane & 3, ox = off2 >> 1, oy = off2 & 1;
    int cidx = g_topk[((size_t)bh * LC + l) * TOPK + cr];
    int py = cidx >> 5, px = cidx & (WCC - 1);
    int pos = (2 * py + ox) * WFF + 2 * px + oy;

    if (lane < 16) {
        int qq = lane >> 2, j = lane & 3;
        int qpos = (2 * lh + (qq >> 1)) * WFF + 2 * lw + (qq & 1);
        float4 qv = ((const float4*)(g_qf + ((size_t)bh * LF + qpos) * DD))[j];
        *reinterpret_cast<float4*>(&sQ[w][qq][4 * j]) = qv;
    }

    const float* kbase = g_kf + (size_t)bh * LF * DD;
    const float* vbase = g_vf + (size_t)bh * LF * DD;
    int cj = lane >> 2, j4 = (lane & 3) * 4;
#pragma unroll
    for (int rep = 0; rep < 4; rep++) {
        int c = rep * 8 + cj;
        int pc = __shfl_sync(0xffffffffu, pos, c);
        float4 kv = *(const float4*)(kbase + (size_t)pc * DD + j4);
        *reinterpret_cast<float4*>(&sKP[w][c][j4]) = kv;
        float4 vv = *(const float4*)(vbase + (size_t)pc * DD + j4);
        *reinterpret_cast<float4*>(&sV[w][c][j4]) = vv;
    }
    __syncwarp();

    const float* kp = &sKP[w][lane][0];
    float4 k0 = *(const float4*)(kp);
    float4 k1 = *(const float4*)(kp + 4);
    float4 k2 = *(const float4*)(kp + 8);
    float4 k3 = *(const float4*)(kp + 12);
    __syncwarp();   // all k regs loaded before P overlays the buffer

    float p[4];
#pragma unroll
    for (int qq = 0; qq < 4; qq++) {
        const float4* q4 = (const float4*)sQ[w][qq];
        float sc = dot16(q4[0], q4[1], q4[2], q4[3], k0, k1, k2, k3);
        float m = sc;
#pragma unroll
        for (int o = 16; o; o >>= 1) m = fmaxf(m, __shfl_xor_sync(0xffffffffu, m, o));
        float e = ex2f(sc - m);
        float s = e;
#pragma unroll
        for (int o = 16; o; o >>= 1) s += __shfl_xor_sync(0xffffffffu, s, o);
        p[qq] = __fdividef(e, s);
    }
    *reinterpret_cast<float4*>(&sKP[w][lane][0]) = make_float4(p[0], p[1], p[2], p[3]);
    __syncwarp();

    int qq = lane >> 3, dp = lane & 7, d0 = dp * 2;
    float accx = 0.f, accy = 0.f;
#pragma unroll
    for (int c = 0; c < 32; c++) {
        float pc = sKP[w][c][qq];
        float2 vv = *reinterpret_cast<const float2*>(&sV[w][c][d0]);
        accx += pc * vv.x;
        accy += pc * vv.y;
    }
    const float* m0p = g_msg0 + ((size_t)bh * LC + l) * DD + d0;
    float o0 = wa * m0p[0] + wb * accx;
    float o1 = wa * m0p[1] + wb * accy;
    int opos = (2 * lh + (qq >> 1)) * WFF + 2 * lw + (qq & 1);
    float* op = out + (((size_t)b * LF + opos) * NH + h) * DD + d0;
    *reinterpret_cast<float2*>(op) = make_float2(o0, o1);
}

extern "C" void kernel_launch(void* const* d_in, const int* in_sizes, int n_in,
                              void* d_out, int out_size) {
    (void)in_sizes; (void)n_in; (void)out_size;
    const float* qf = (const float*)d_in[0];
    const float* qc = (const float*)d_in[1];
    const float* kf = (const float*)d_in[2];
    const float* kc = (const float*)d_in[3];
    const float* vf = (const float*)d_in[4];
    const float* vc = (const float*)d_in[5];
    const float* wt = (const float*)d_in[6];
    float* out = (float*)d_out;

    void *p_qc, *p_kc, *p_vc, *p_qf, *p_kf, *p_vf;
    cudaGetSymbolAddress(&p_qc, g_qc);
    cudaGetSymbolAddress(&p_kc, g_kc);
    cudaGetSymbolAddress(&p_vc, g_vc);
    cudaGetSymbolAddress(&p_qf, g_qf);
    cudaGetSymbolAddress(&p_kf, g_kf);
    cudaGetSymbolAddress(&p_vf, g_vf);

    const float qscale = 0.25f * 1.4426950408889634f;  // temp * log2(e)
    transpose3_kernel<<<dim3(LC / 256, 32, 3), 256>>>(
        qc, kc, vc, (float*)p_qc, (float*)p_kc, (float*)p_vc, LC, qscale);
    transpose3_kernel<<<dim3(LF / 256, 32, 3), 256>>>(
        qf, kf, vf, (float*)p_qf, (float*)p_kf, (float*)p_vf, LF, qscale);

    cudaFuncSetAttribute(coarse_kernel, cudaFuncAttributeMaxDynamicSharedMemorySize,
                         CSMEM_BYTES);
    coarse_kernel<<<dim3(4, 32), 256, CSMEM_BYTES>>>();

    fine_kernel<<<4096, 256>>>(wt, out);
}

// round 15
// speedup vs baseline: 1.5545x; 1.0002x over previous
#include <cuda_runtime.h>

#define BB 4
#define NH 8
#define DD 16
#define LC 1024
#define WCC 32
#define LF 4096
#define WFF 64
#define TOPK 8
#define KVPAD 20

typedef unsigned long long ull;

__device__ float g_qc[BB*NH*LC*DD];
__device__ float g_kc[BB*NH*LC*DD];
__device__ float g_vc[BB*NH*LC*DD];
__device__ float g_qf[BB*NH*LF*DD];
__device__ float g_kf[BB*NH*LF*DD];
__device__ float g_vf[BB*NH*LF*DD];
__device__ float g_msg0[BB*NH*LC*DD];
__device__ int   g_topk[BB*NH*LC*TOPK];

__device__ __forceinline__ float2 f2unpack(ull v) {
    float lo, hi; asm("mov.b64 {%0, %1}, %2;" : "=f"(lo), "=f"(hi) : "l"(v));
    return make_float2(lo, hi);
}
__device__ __forceinline__ ull f2dup(float x) {
    ull r; asm("mov.b64 %0, {%1, %1};" : "=l"(r) : "f"(x)); return r;
}
__device__ __forceinline__ ull f2fma(ull a, ull b, ull c) {
    ull d; asm("fma.rn.f32x2 %0, %1, %2, %3;" : "=l"(d) : "l"(a), "l"(b), "l"(c));
    return d;
}
__device__ __forceinline__ ull f2add(ull a, ull b) {
    ull d; asm("add.rn.f32x2 %0, %1, %2;" : "=l"(d) : "l"(a), "l"(b));
    return d;
}
__device__ __forceinline__ float ex2f(float x) {
    float r; asm("ex2.approx.ftz.f32 %0, %1;" : "=f"(r) : "f"(x)); return r;
}

// ---------------- tiled transpose: [BH,16,P] -> [BH,P,16] ----------------
__global__ void __launch_bounds__(256) transpose3_kernel(
        const float* __restrict__ q, const float* __restrict__ k,
        const float* __restrict__ v, float* __restrict__ oq,
        float* __restrict__ ok, float* __restrict__ ov, int P, float qscale) {
    __shared__ float tile[16 * 260];
    int z = blockIdx.z;
    const float* in = (z == 0) ? q : (z == 1) ? k : v;
    float* out = (z == 0) ? oq : (z == 1) ? ok : ov;
    float scale = (z == 0) ? qscale : 1.f;
    int bh = blockIdx.y, p0 = blockIdx.x * 256, t = threadIdx.x;
    const float4* src = reinterpret_cast<const float4*>(in + (size_t)bh * DD * P + p0);
    int Pq = P >> 2;
#pragma unroll
    for (int j = 0; j < 4; j++) {
        int f = t + 256 * j;
        int d = f >> 6, c4 = f & 63;
        float4 val = src[(size_t)d * Pq + c4];
        val.x *= scale; val.y *= scale; val.z *= scale; val.w *= scale;
        *reinterpret_cast<float4*>(&tile[d * 260 + c4 * 4]) = val;
    }
    __syncthreads();
    float o[16];
#pragma unroll
    for (int d = 0; d < 16; d++) o[d] = tile[d * 260 + t];
    float4* dst = reinterpret_cast<float4*>(out + ((size_t)bh * P + p0 + t) * DD);
    dst[0] = make_float4(o[0], o[1], o[2], o[3]);
    dst[1] = make_float4(o[4], o[5], o[6], o[7]);
    dst[2] = make_float4(o[8], o[9], o[10], o[11]);
    dst[3] = make_float4(o[12], o[13], o[14], o[15]);
}

// ---------------- coarse: lane-per-row, explicit 2-stage pipeline --------
#define CSMEM_BYTES (2 * LC * DD * 4)

// 64B row via 4x LDS.128 (guaranteed vector loads)
__device__ __forceinline__ void loadrow2(const float* __restrict__ p, ull* r) {
    const ulonglong2* u = (const ulonglong2*)p;
    ulonglong2 x0 = u[0], x1 = u[1], x2 = u[2], x3 = u[3];
    r[0] = x0.x; r[1] = x0.y; r[2] = x1.x; r[3] = x1.y;
    r[4] = x2.x; r[5] = x2.y; r[6] = x3.x; r[7] = x3.y;
}

struct CoarseState {
    ull q[8];
    ull acc[8];
    float sum;
    float tv[8];
    int tc[8];
};

__device__ __forceinline__ void coarse_step(CoarseState& st, const ull* kr,
                                            const ull* vr, int j) {
    ull a0 = 0ull, a1 = 0ull;
    a0 = f2fma(st.q[0], kr[0], a0); a1 = f2fma(st.q[1], kr[1], a1);
    a0 = f2fma(st.q[2], kr[2], a0); a1 = f2fma(st.q[3], kr[3], a1);
    a0 = f2fma(st.q[4], kr[4], a0); a1 = f2fma(st.q[5], kr[5], a1);
    a0 = f2fma(st.q[6], kr[6], a0); a1 = f2fma(st.q[7], kr[7], a1);
    float2 u = f2unpack(f2add(a0, a1));
    float sc = u.x + u.y;
    float e = ex2f(sc);            // log2e folded into Q scale
    st.sum += e;
    ull ed = f2dup(e);
#pragma unroll
    for (int dp = 0; dp < 8; dp++) st.acc[dp] = f2fma(ed, vr[dp], st.acc[dp]);
    // exact top-8: strict > + ascending j == lax.top_k tie semantics
    if (sc > st.tv[7]) {
        st.tv[7] = sc; st.tc[7] = j;
#pragma unroll
        for (int k = 7; k >= 1; k--) {
            bool sw = st.tv[k] > st.tv[k - 1];
            float va = sw ? st.tv[k - 1] : st.tv[k];
            float vb = sw ? st.tv[k] : st.tv[k - 1];
            int ia = sw ? st.tc[k - 1] : st.tc[k];
            int ib = sw ? st.tc[k] : st.tc[k - 1];
            st.tv[k] = va; st.tv[k - 1] = vb;
            st.tc[k] = ia; st.tc[k - 1] = ib;
        }
    }
}

__global__ void __launch_bounds__(256, 1) coarse_kernel() {
    extern __shared__ float sm[];
    float* sK = sm;             // 1024 x 16, contiguous (broadcast reads)
    float* sV = sm + LC * DD;   // 1024 x 16
    int tid = threadIdx.x, w = tid >> 5, lane = tid & 31;
    int bh = blockIdx.y;

    {
        const float4* K4 = (const float4*)(g_kc + (size_t)bh * LC * DD);
        const float4* V4 = (const float4*)(g_vc + (size_t)bh * LC * DD);
        float4* sK4 = (float4*)sK;
        float4* sV4 = (float4*)sV;
#pragma unroll
        for (int i = tid; i < LC * DD / 4; i += 256) {
            sK4[i] = K4[i];
            sV4[i] = V4[i];
        }
    }

    int row = blockIdx.x * 256 + w * 32 + lane;
    const ull* Qg = (const ull*)(g_qc + ((size_t)bh * LC + row) * DD);
    CoarseState st;
#pragma unroll
    for (int dp = 0; dp < 8; dp++) st.q[dp] = Qg[dp];
#pragma unroll
    for (int dp = 0; dp < 8; dp++) st.acc[dp] = 0ull;
#pragma unroll
    for (int k = 0; k < 8; k++) { st.tv[k] = -3e38f; st.tc[k] = 0; }
    st.sum = 0.f;
    __syncthreads();

    // explicit 2-stage double buffer: no rotation copies, loads lead math
    ull ka[8], va[8], kb[8], vb[8];
    loadrow2(sK, ka);
    loadrow2(sV, va);

#pragma unroll 1
    for (int j = 0; j < LC; j += 2) {
        loadrow2(sK + (j + 1) * DD, kb);
        loadrow2(sV + (j + 1) * DD, vb);
        coarse_step(st, ka, va, j);
        int jn = (j + 2) & (LC - 1);
        loadrow2(sK + jn * DD, ka);
        loadrow2(sV + jn * DD, va);
        coarse_step(st, kb, vb, j + 1);
    }

    int* tb = g_topk + ((size_t)bh * LC + row) * TOPK;
    *(int4*)tb = make_int4(st.tc[0], st.tc[1], st.tc[2], st.tc[3]);
    *(int4*)(tb + 4) = make_int4(st.tc[4], st.tc[5], st.tc[6], st.tc[7]);

    float rs = 1.f / st.sum;
    float o[16];
#pragma unroll
    for (int dp = 0; dp < 8; dp++) {
        float2 u = f2unpack(st.acc[dp]);
        o[2 * dp] = u.x * rs;
        o[2 * dp + 1] = u.y * rs;
    }
    float4* mp = (float4*)(g_msg0 + ((size_t)bh * LC + row) * DD);
    mp[0] = make_float4(o[0], o[1], o[2], o[3]);
    mp[1] = make_float4(o[4], o[5], o[6], o[7]);
    mp[2] = make_float4(o[8], o[9], o[10], o[11]);
    mp[3] = make_float4(o[12], o[13], o[14], o[15]);
}

// ---------------- fine level + combine ----------------
__device__ __forceinline__ float dot16(float4 a0, float4 a1, float4 a2, float4 a3,
                                       float4 b0, float4 b1, float4 b2, float4 b3) {
    float s = a0.x*b0.x + a0.y*b0.y + a0.z*b0.z + a0.w*b0.w;
    s += a1.x*b1.x + a1.y*b1.y + a1.z*b1.z + a1.w*b1.w;
    s += a2.x*b2.x + a2.y*b2.y + a2.z*b2.z + a2.w*b2.w;
    s += a3.x*b3.x + a3.y*b3.y + a3.z*b3.z + a3.w*b3.w;
    return s;
}

__global__ void __launch_bounds__(256) fine_kernel(const float* __restrict__ wptr,
                                                   float* __restrict__ out) {
    __shared__ float sQ[8][4][16];
    __shared__ float sKP[8][32][KVPAD];   // K tiles, later overlaid by P
    __shared__ float sV[8][32][KVPAD];
    int tid = threadIdx.x, w = tid >> 5, lane = tid & 31;
    int gw = blockIdx.x * 8 + w;
    int bh = gw >> 10, l = gw & 1023;
    int b = bh >> 3, h = bh & 7;
    int lh = l >> 5, lw = l & 31;

    float w0 = wptr[0], w1 = wptr[1];
    float mw = fmaxf(w0, w1);
    float ew0 = __expf(w0 - mw), ew1 = __expf(w1 - mw);
    float rw = __fdividef(1.f, ew0 + ew1);
    float wa = ew0 * rw, wb = ew1 * rw;

    int cr = lane >> 2, off2 = lane & 3, ox = off2 >> 1, oy = off2 & 1;
    int cidx = g_topk[((size_t)bh * LC + l) * TOPK + cr];
    int py = cidx >> 5, px = cidx & (WCC - 1);
    int pos = (2 * py + ox) * WFF + 2 * px + oy;

    if (lane < 16) {
        int qq = lane >> 2, j = lane & 3;
        int qpos = (2 * lh + (qq >> 1)) * WFF + 2 * lw + (qq & 1);
        float4 qv = ((const float4*)(g_qf + ((size_t)bh * LF + qpos) * DD))[j];
        *reinterpret_cast<float4*>(&sQ[w][qq][4 * j]) = qv;
    }

    const float* kbase = g_kf + (size_t)bh * LF * DD;
    const float* vbase = g_vf + (size_t)bh * LF * DD;
    int cj = lane >> 2, j4 = (lane & 3) * 4;
#pragma unroll
    for (int rep = 0; rep < 4; rep++) {
        int c = rep * 8 + cj;
        int pc = __shfl_sync(0xffffffffu, pos, c);
        float4 kv = *(const float4*)(kbase + (size_t)pc * DD + j4);
        *reinterpret_cast<float4*>(&sKP[w][c][j4]) = kv;
        float4 vv = *(const float4*)(vbase + (size_t)pc * DD + j4);
        *reinterpret_cast<float4*>(&sV[w][c][j4]) = vv;
    }
    __syncwarp();

    const float* kp = &sKP[w][lane][0];
    float4 k0 = *(const float4*)(kp);
    float4 k1 = *(const float4*)(kp + 4);
    float4 k2 = *(const float4*)(kp + 8);
    float4 k3 = *(const float4*)(kp + 12);
    __syncwarp();   // all k regs loaded before P overlays the buffer

    float p[4];
#pragma unroll
    for (int qq = 0; qq < 4; qq++) {
        const float4* q4 = (const float4*)sQ[w][qq];
        float sc = dot16(q4[0], q4[1], q4[2], q4[3], k0, k1, k2, k3);
        float m = sc;
#pragma unroll
        for (int o = 16; o; o >>= 1) m = fmaxf(m, __shfl_xor_sync(0xffffffffu, m, o));
        float e = ex2f(sc - m);
        float s = e;
#pragma unroll
        for (int o = 16; o; o >>= 1) s += __shfl_xor_sync(0xffffffffu, s, o);
        p[qq] = __fdividef(e, s);
    }
    *reinterpret_cast<float4*>(&sKP[w][lane][0]) = make_float4(p[0], p[1], p[2], p[3]);
    __syncwarp();

    int qq = lane >> 3, dp = lane & 7, d0 = dp * 2;
    float accx = 0.f, accy = 0.f;
#pragma unroll
    for (int c = 0; c < 32; c++) {
        float pc = sKP[w][c][qq];
        float2 vv = *reinterpret_cast<const float2*>(&sV[w][c][d0]);
        accx += pc * vv.x;
        accy += pc * vv.y;
    }
    const float* m0p = g_msg0 + ((size_t)bh * LC + l) * DD + d0;
    float o0 = wa * m0p[0] + wb * accx;
    float o1 = wa * m0p[1] + wb * accy;
    int opos = (2 * lh + (qq >> 1)) * WFF + 2 * lw + (qq & 1);
    float* op = out + (((size_t)b * LF + opos) * NH + h) * DD + d0;
    *reinterpret_cast<float2*>(op) = make_float2(o0, o1);
}

extern "C" void kernel_launch(void* const* d_in, const int* in_sizes, int n_in,
                              void* d_out, int out_size) {
    (void)in_sizes; (void)n_in; (void)out_size;
    const float* qf = (const float*)d_in[0];
    const float* qc = (const float*)d_in[1];
    const float* kf = (const float*)d_in[2];
    const float* kc = (const float*)d_in[3];
    const float* vf = (const float*)d_in[4];
    const float* vc = (const float*)d_in[5];
    const float* wt = (const float*)d_in[6];
    float* out = (float*)d_out;

    void *p_qc, *p_kc, *p_vc, *p_qf, *p_kf, *p_vf;
    cudaGetSymbolAddress(&p_qc, g_qc);
    cudaGetSymbolAddress(&p_kc, g_kc);
    cudaGetSymbolAddress(&p_vc, g_vc);
    cudaGetSymbolAddress(&p_qf, g_qf);
    cudaGetSymbolAddress(&p_kf, g_kf);
    cudaGetSymbolAddress(&p_vf, g_vf);

    const float qscale = 0.25f * 1.4426950408889634f;  // temp * log2(e)
    transpose3_kernel<<<dim3(LC / 256, 32, 3), 256>>>(
        qc, kc, vc, (float*)p_qc, (float*)p_kc, (float*)p_vc, LC, qscale);
    transpose3_kernel<<<dim3(LF / 256, 32, 3), 256>>>(
        qf, kf, vf, (float*)p_qf, (float*)p_kf, (float*)p_vf, LF, qscale);

    cudaFuncSetAttribute(coarse_kernel, cudaFuncAttributeMaxDynamicSharedMemorySize,
                         CSMEM_BYTES);
    coarse_kernel<<<dim3(4, 32), 256, CSMEM_BYTES>>>();

    fine_kernel<<<4096, 256>>>(wt, out);
}